// round 9
// baseline (speedup 1.0000x reference)
#include <cuda_runtime.h>

#define BATCH 8
#define CH    512
#define HW    4096
#define NMASK 1024
#define NCTX  3072
#define EPSF  1e-8f
#define NSPLIT 4

// ---------------- scratch ----------------------------------------------------
__device__ float g_Am[BATCH * CH * NMASK];            // [b][k][i] fp32
__device__ float g_Bn[BATCH * CH * NCTX];             // [b][k][j] fp32
__device__ float g_A3[3][BATCH * CH * NMASK];         // tf32 h/m/l planes
__device__ float g_B3[3][BATCH * CH * NCTX];
__device__ float g_best[BATCH * NMASK * CH];
__device__ float g_mskn[BATCH * NMASK * CH];
__device__ float g_gen[BATCH * NMASK * CH];
__device__ float g_part[NSPLIT][BATCH * HW];
__device__ float g_invall[BATCH * HW];
__device__ float g_invc[BATCH * NCTX];
__device__ float g_invm[BATCH * NMASK];
__device__ float g_maxc[BATCH * NMASK];
__device__ unsigned long long g_packed[BATCH * NMASK];
__device__ int   g_imask[HW];

// ---------------- helpers ----------------------------------------------------
__device__ __forceinline__ void cp16(void* sdst, const void* gsrc) {
    unsigned saddr = (unsigned)__cvta_generic_to_shared(sdst);
    asm volatile("cp.async.ca.shared.global [%0], [%1], 16;\n" :: "r"(saddr), "l"(gsrc));
}
__device__ __forceinline__ unsigned ford(float f) {
    unsigned u = __float_as_uint(f);
    return (u & 0x80000000u) ? ~u : (u | 0x80000000u);
}
__device__ __forceinline__ float frcp(float x) {
    float r; asm("rcp.approx.f32 %0, %1;" : "=f"(r) : "f"(x)); return r;
}
__device__ __forceinline__ float frsq(float x) {
    float r; asm("rsqrt.approx.f32 %0, %1;" : "=f"(r) : "f"(x)); return r;
}
__device__ __forceinline__ void tf32_split(float v, float& h, float& m, float& l) {
    unsigned hb; asm("cvt.rna.tf32.f32 %0, %1;" : "=r"(hb) : "f"(v));
    h = __uint_as_float(hb);
    float r1 = v - h;
    unsigned mb; asm("cvt.rna.tf32.f32 %0, %1;" : "=r"(mb) : "f"(r1));
    m = __uint_as_float(mb);
    float r2 = r1 - m;
    unsigned lb; asm("cvt.rna.tf32.f32 %0, %1;" : "=r"(lb) : "f"(r2));
    l = __uint_as_float(lb);
}

// ---------------- K1a/K1b: column norms -------------------------------------
__global__ void k_part(const float* __restrict__ x) {
    int p = blockIdx.x * 256 + threadIdx.x;
    int b = blockIdx.y;
    int z = blockIdx.z;
    const float* base = x + ((size_t)b * CH + (size_t)z * (CH / NSPLIT)) * HW + p;
    float s = 0.f;
#pragma unroll 8
    for (int c = 0; c < CH / NSPLIT; c++) {
        float v = base[(size_t)c * HW];
        s += v * v;
    }
    g_part[z][b * HW + p] = s;
}
__global__ void k_invall() {
    int i = blockIdx.x * 256 + threadIdx.x;
    float s = g_part[0][i] + g_part[1][i] + g_part[2][i] + g_part[3][i];
    g_invall[i] = 1.f / (sqrtf(s) + EPSF);
}

// ---------------- K2: setup --------------------------------------------------
__global__ void k_setup(const int* __restrict__ np, const int* __restrict__ mp) {
    int t = threadIdx.x;  // 1024, 1 block
    for (int p = t; p < HW; p += 1024) g_imask[p] = -1;
    __syncthreads();
    g_imask[mp[t]] = t;
    for (int i = t; i < BATCH * NMASK; i += 1024) g_packed[i] = 0ull;
    for (int i = t; i < BATCH * NMASK; i += 1024) {
        int b = i / NMASK;
        g_invm[i] = g_invall[b * HW + mp[i % NMASK]];
    }
    for (int j = t; j < BATCH * NCTX; j += 1024) {
        int b = j / NCTX;
        g_invc[j] = g_invall[b * HW + np[j % NCTX]];
    }
}

// ---------------- K3: gather + tf32 3-way split ------------------------------
__global__ void k_gather(const float* __restrict__ x,
                         const int* __restrict__ np, const int* __restrict__ mp) {
    int k = blockIdx.x;
    int b = blockIdx.y;
    int t = threadIdx.x;        // 1024
    const float* row = x + ((size_t)b * CH + k) * HW;
    size_t oa = ((size_t)b * CH + k) * NMASK;
    float h, m, l;
    float v = row[mp[t]];
    g_Am[oa + t] = v;
    tf32_split(v, h, m, l);
    g_A3[0][oa + t] = h; g_A3[1][oa + t] = m; g_A3[2][oa + t] = l;
    size_t ob = ((size_t)b * CH + k) * NCTX;
#pragma unroll
    for (int j = t; j < NCTX; j += 1024) {
        float w = row[np[j]];
        g_Bn[ob + j] = w;
        tf32_split(w, h, m, l);
        g_B3[0][ob + j] = h; g_B3[1][ob + j] = m; g_B3[2][ob + j] = l;
    }
}

// ---------------- K4: tf32 mma.sync GEMM (3-way split, 6 products) ----------
#define KCH 32
#define NKT (CH / KCH)            // 16
#define PLW (32 * 132)            // plane stride in floats (pad 132)
#define STW (6 * PLW)             // stage stride
#define SMEM_BYTES ((2 * STW + 128) * 4)

__device__ __forceinline__ void fill_stage(float* smbase, int k0, int b,
                                           int i0, int j0, int tid) {
#pragma unroll
    for (int q = 0; q < 24; q++) {
        int c  = q * 256 + tid;       // 0..6143
        int pl = c >> 10;             // 0..5
        int rr = (c >> 5) & 31;       // k row
        int ch = c & 31;              // 16B chunk
        const float* src;
        if (pl < 3) src = g_A3[pl]   + ((size_t)b * CH + (k0 + rr)) * NMASK + i0 + ch * 4;
        else        src = g_B3[pl-3] + ((size_t)b * CH + (k0 + rr)) * NCTX  + j0 + ch * 4;
        cp16(smbase + pl * PLW + rr * 132 + ch * 4, src);
    }
}

__global__ void __launch_bounds__(256, 1) k_tgemm() {
    extern __shared__ float sm[];
    int b  = blockIdx.z;
    int i0 = blockIdx.y * 128;
    int j0 = blockIdx.x * 128;
    int tid = threadIdx.x;
    int wid = tid >> 5, lane = tid & 31;
    int t4 = lane & 3, g = lane >> 2;
    int wm = wid & 3, wn = wid >> 2;
    int m0 = wm * 32, n0 = wn * 64;

    float acc[2][8][4];
#pragma unroll
    for (int mt = 0; mt < 2; mt++)
#pragma unroll
        for (int nt = 0; nt < 8; nt++)
#pragma unroll
            for (int c = 0; c < 4; c++) acc[mt][nt][c] = 0.f;

    float* sInvc = sm + 2 * STW;
    if (tid < 128) sInvc[tid] = g_invc[b * NCTX + j0 + tid];

    fill_stage(sm, 0, b, i0, j0, tid);
    asm volatile("cp.async.commit_group;\n");
    fill_stage(sm + STW, KCH, b, i0, j0, tid);
    asm volatile("cp.async.commit_group;\n");

    const int PA[6] = {0, 0, 1, 1, 0, 2};
    const int PB[6] = {0, 1, 0, 1, 2, 0};

#pragma unroll 1
    for (int t = 0; t < NKT; t++) {
        if (t < NKT - 1) asm volatile("cp.async.wait_group 1;\n");
        else             asm volatile("cp.async.wait_group 0;\n");
        __syncthreads();
        float* st = sm + (t & 1) * STW;
#pragma unroll
        for (int kk = 0; kk < KCH; kk += 8) {
            float a[3][2][4];
#pragma unroll
            for (int p = 0; p < 3; p++) {
                const float* pA = st + p * PLW;
#pragma unroll
                for (int mt = 0; mt < 2; mt++) {
                    int mb = m0 + mt * 16 + g;
                    a[p][mt][0] = pA[(kk + t4) * 132 + mb];
                    a[p][mt][1] = pA[(kk + t4) * 132 + mb + 8];
                    a[p][mt][2] = pA[(kk + t4 + 4) * 132 + mb];
                    a[p][mt][3] = pA[(kk + t4 + 4) * 132 + mb + 8];
                }
            }
            float bv[3][8][2];
#pragma unroll
            for (int p = 0; p < 3; p++) {
                const float* pB = st + (3 + p) * PLW;
#pragma unroll
                for (int nt = 0; nt < 8; nt++) {
                    int nb = n0 + nt * 8 + g;
                    bv[p][nt][0] = pB[(kk + t4) * 132 + nb];
                    bv[p][nt][1] = pB[(kk + t4 + 4) * 132 + nb];
                }
            }
#pragma unroll
            for (int pr = 0; pr < 6; pr++) {
                int pa = PA[pr], pb = PB[pr];
#pragma unroll
                for (int mt = 0; mt < 2; mt++)
#pragma unroll
                    for (int nt = 0; nt < 8; nt++) {
                        asm volatile(
                            "mma.sync.aligned.m16n8k8.row.col.f32.tf32.tf32.f32 "
                            "{%0,%1,%2,%3},{%4,%5,%6,%7},{%8,%9},{%0,%1,%2,%3};"
                            : "+f"(acc[mt][nt][0]), "+f"(acc[mt][nt][1]),
                              "+f"(acc[mt][nt][2]), "+f"(acc[mt][nt][3])
                            : "r"(__float_as_uint(a[pa][mt][0])),
                              "r"(__float_as_uint(a[pa][mt][1])),
                              "r"(__float_as_uint(a[pa][mt][2])),
                              "r"(__float_as_uint(a[pa][mt][3])),
                              "r"(__float_as_uint(bv[pb][nt][0])),
                              "r"(__float_as_uint(bv[pb][nt][1])));
                    }
            }
        }
        __syncthreads();
        if (t + 2 < NKT) {
            fill_stage(sm + (t & 1) * STW, (t + 2) * KCH, b, i0, j0, tid);
            asm volatile("cp.async.commit_group;\n");
        }
    }

    // epilogue: scale + row argmax; thread rows: m0 + mt*16 + half*8 + g
#pragma unroll
    for (int mt = 0; mt < 2; mt++)
#pragma unroll
        for (int half = 0; half < 2; half++) {
            unsigned long long bp = 0ull;
#pragma unroll
            for (int nt = 0; nt < 8; nt++)
#pragma unroll
                for (int c = 0; c < 2; c++) {
                    int jl = n0 + nt * 8 + t4 * 2 + c;
                    float v = acc[mt][nt][half * 2 + c] * sInvc[jl];
                    int jg = j0 + jl;
                    unsigned long long pk =
                        ((unsigned long long)ford(v) << 32) | (unsigned)(~(unsigned)jg);
                    if (pk > bp) bp = pk;
                }
            unsigned long long o1 = __shfl_xor_sync(0xffffffffu, bp, 1); if (o1 > bp) bp = o1;
            unsigned long long o2 = __shfl_xor_sync(0xffffffffu, bp, 2); if (o2 > bp) bp = o2;
            if (t4 == 0) {
                int row = i0 + m0 + mt * 16 + half * 8 + g;
                atomicMax(&g_packed[b * NMASK + row], bp);
            }
        }
}

// ---------------- K5: finalize pick + gather from L2-hot scratch ------------
__global__ void k_finalize() {
    int i = blockIdx.x;
    int b = blockIdx.y;
    int t = threadIdx.x;  // 256
    __shared__ int s_j;
    __shared__ float s_invm;
    if (t == 0) {
        unsigned long long pk = g_packed[b * NMASK + i];
        unsigned j  = ~(unsigned)pk;
        unsigned ov = (unsigned)(pk >> 32);
        unsigned fb = (ov & 0x80000000u) ? (ov & 0x7fffffffu) : ~ov;
        float val = __uint_as_float(fb);
        float im  = g_invm[b * NMASK + i];
        g_maxc[b * NMASK + i] = val * im;
        s_j = (int)j;
        s_invm = im;
    }
    __syncthreads();
    int jj = s_j;
    float im = s_invm;
    const float* Am = g_Am + (size_t)b * CH * NMASK;
    const float* Bn = g_Bn + (size_t)b * CH * NCTX;
    size_t o = ((size_t)b * NMASK + i) * CH;
#pragma unroll
    for (int c = t; c < CH; c += 256) {
        g_best[o + c] = Bn[(size_t)c * NCTX + jj];
        g_mskn[o + c] = Am[(size_t)c * NMASK + i] * im;
    }
}

// ---------------- K6: dual-chain ILP scan (4 blocks x 1 warp x 2 batches) ---
#define SST 4

__global__ void __launch_bounds__(32, 1) k_scan() {
    __shared__ __align__(16) float ring[2][SST][2][CH];   // 32KB

    int bp = blockIdx.x;          // 0..3
    int lane = threadIdx.x;
    int bA = bp * 2, bB = bp * 2 + 1;

    const float* MNA = g_mskn + (size_t)bA * NMASK * CH;
    const float* BSA = g_best + (size_t)bA * NMASK * CH;
    float*       GEA = g_gen  + (size_t)bA * NMASK * CH;
    const float* MXA = g_maxc + bA * NMASK;
    const float* MNB = g_mskn + (size_t)bB * NMASK * CH;
    const float* BSB = g_best + (size_t)bB * NMASK * CH;
    float*       GEB = g_gen  + (size_t)bB * NMASK * CH;
    const float* MXB = g_maxc + bB * NMASK;
    size_t lo = (size_t)lane * 16;

#define PRE1(MN, BS, ch, i, s)                                                \
    do {                                                                      \
        const float* pm = (MN) + (size_t)(i) * CH + lo;                       \
        const float* pb = (BS) + (size_t)(i) * CH + lo;                       \
        cp16(&ring[ch][s][0][lo],      pm);                                   \
        cp16(&ring[ch][s][0][lo + 4],  pm + 4);                               \
        cp16(&ring[ch][s][0][lo + 8],  pm + 8);                               \
        cp16(&ring[ch][s][0][lo + 12], pm + 12);                              \
        cp16(&ring[ch][s][1][lo],      pb);                                   \
        cp16(&ring[ch][s][1][lo + 4],  pb + 4);                               \
        cp16(&ring[ch][s][1][lo + 8],  pb + 8);                               \
        cp16(&ring[ch][s][1][lo + 12], pb + 12);                              \
    } while (0)

#pragma unroll
    for (int s = 0; s < SST; s++) {
        PRE1(MNA, BSA, 0, s, s);
        PRE1(MNB, BSB, 1, s, s);
        asm volatile("cp.async.commit_group;\n");
    }

    float qA[16], qB[16];
#pragma unroll
    for (int e = 0; e < 16; e++) { qA[e] = 0.f; qB[e] = 0.f; }
    float mxA0 = MXA[0], mxB0 = MXB[0];

#pragma unroll 1
    for (int i = 0; i < NMASK; i++) {
        int s = i & (SST - 1);
        float mxA = mxA0, mxB = mxB0;
        mxA0 = (i + 1 < NMASK) ? MXA[i + 1] : 0.f;
        mxB0 = (i + 1 < NMASK) ? MXB[i + 1] : 0.f;

        asm volatile("cp.async.wait_group %0;\n" :: "n"(SST - 1));

        float mnA[16], bsA[16], mnB[16], bsB[16];
#pragma unroll
        for (int u = 0; u < 4; u++) {
            float4 a = *(const float4*)&ring[0][s][0][lo + u * 4];
            mnA[u*4+0]=a.x; mnA[u*4+1]=a.y; mnA[u*4+2]=a.z; mnA[u*4+3]=a.w;
            float4 c = *(const float4*)&ring[0][s][1][lo + u * 4];
            bsA[u*4+0]=c.x; bsA[u*4+1]=c.y; bsA[u*4+2]=c.z; bsA[u*4+3]=c.w;
            float4 d = *(const float4*)&ring[1][s][0][lo + u * 4];
            mnB[u*4+0]=d.x; mnB[u*4+1]=d.y; mnB[u*4+2]=d.z; mnB[u*4+3]=d.w;
            float4 e = *(const float4*)&ring[1][s][1][lo + u * 4];
            bsB[u*4+0]=e.x; bsB[u*4+1]=e.y; bsB[u*4+2]=e.z; bsB[u*4+3]=e.w;
        }

        if (i + SST < NMASK) {
            PRE1(MNA, BSA, 0, i + SST, s);
            PRE1(MNB, BSB, 1, i + SST, s);
        }
        asm volatile("cp.async.commit_group;\n");

        float p1A[8], p2A[8], p1B[8], p2B[8];
#pragma unroll
        for (int e = 0; e < 8; e++) {
            p1A[e] = __fmaf_rn(qA[e], qA[e], qA[e + 8] * qA[e + 8]);
            p1B[e] = __fmaf_rn(qB[e], qB[e], qB[e + 8] * qB[e + 8]);
            p2A[e] = __fmaf_rn(mnA[e], qA[e], mnA[e + 8] * qA[e + 8]);
            p2B[e] = __fmaf_rn(mnB[e], qB[e], mnB[e + 8] * qB[e + 8]);
        }
#pragma unroll
        for (int w = 4; w; w >>= 1)
#pragma unroll
            for (int e = 0; e < w; e++) {
                p1A[e] += p1A[e + w]; p1B[e] += p1B[e + w];
                p2A[e] += p2A[e + w]; p2B[e] += p2B[e + w];
            }
        float s1A = p1A[0], s2A = p2A[0], s1B = p1B[0], s2B = p2B[0];
#pragma unroll
        for (int o = 16; o; o >>= 1) {
            s1A += __shfl_xor_sync(0xffffffffu, s1A, o);
            s1B += __shfl_xor_sync(0xffffffffu, s1B, o);
            s2A += __shfl_xor_sync(0xffffffffu, s2A, o);
            s2B += __shfl_xor_sync(0xffffffffu, s2B, o);
        }
        float rA = (s1A > 0.f) ? frsq(s1A) : 0.f;
        float rB = (s1B > 0.f) ? frsq(s1B) : 0.f;
        float nA = s1A * rA,            nB = s1B * rB;
        float uA = __fmaf_rn(mxA, nA, mxA * EPSF);
        float uB = __fmaf_rn(mxB, nB, mxB * EPSF);
        float sA = fmaxf(s2A, 0.f),     sB = fmaxf(s2B, 0.f);
        float TA = __fmaf_rn(EPSF, nA, sA + uA);
        float TB = __fmaf_rn(EPSF, nB, sB + uB);
        float rTA = frcp(TA),           rTB = frcp(TB);
        float w1A = sA * rTA, w2A = uA * rTA;
        float w1B = sB * rTB, w2B = uB * rTB;
#pragma unroll
        for (int e = 0; e < 16; e++) {
            qA[e] = __fmaf_rn(w1A, qA[e], w2A * bsA[e]);
            qB[e] = __fmaf_rn(w1B, qB[e], w2B * bsB[e]);
        }
        float* geA = GEA + (size_t)i * CH + lo;
        float* geB = GEB + (size_t)i * CH + lo;
#pragma unroll
        for (int u = 0; u < 4; u++) {
            float4 w;
            w.x = qA[u*4+0]; w.y = qA[u*4+1]; w.z = qA[u*4+2]; w.w = qA[u*4+3];
            *(float4*)(geA + u * 4) = w;
            float4 v;
            v.x = qB[u*4+0]; v.y = qB[u*4+1]; v.z = qB[u*4+2]; v.w = qB[u*4+3];
            *(float4*)(geB + u * 4) = v;
        }
    }
}

// ---------------- K7: assemble output ---------------------------------------
__global__ void k_out(const float* __restrict__ x, float* __restrict__ out) {
    int idx = blockIdx.x * 256 + threadIdx.x;
    int p = idx & (HW - 1);
    int c = (idx >> 12) & (CH - 1);
    int b = idx >> 21;
    int mi = g_imask[p];
    float v = (mi >= 0) ? g_gen[(((size_t)b * NMASK) + mi) * CH + c] : x[idx];
    out[idx] = v;
}

// ---------------- launch -----------------------------------------------------
extern "C" void kernel_launch(void* const* d_in, const int* in_sizes, int n_in,
                              void* d_out, int out_size) {
    const float* x  = (const float*)d_in[0];
    const int*   np = (const int*)d_in[2];
    const int*   mp = (const int*)d_in[3];
    float*       out = (float*)d_out;

    cudaFuncSetAttribute(k_tgemm, cudaFuncAttributeMaxDynamicSharedMemorySize, SMEM_BYTES);

    k_part    <<<dim3(HW / 256, BATCH, NSPLIT), 256>>>(x);
    k_invall  <<<BATCH * HW / 256, 256>>>();
    k_setup   <<<1, 1024>>>(np, mp);
    k_gather  <<<dim3(CH, BATCH), 1024>>>(x, np, mp);
    k_tgemm   <<<dim3(NCTX / 128, NMASK / 128, BATCH), 256, SMEM_BYTES>>>();
    k_finalize<<<dim3(NMASK, BATCH), 256>>>();
    k_scan    <<<BATCH / 2, 32>>>();
    k_out     <<<(BATCH * CH * HW) / 256, 256>>>(x, out);
}

// round 10
// speedup vs baseline: 1.9643x; 1.9643x over previous
#include <cuda_runtime.h>

#define BATCH 8
#define CH    512
#define HW    4096
#define NMASK 1024
#define NCTX  3072
#define EPSF  1e-8f
#define NSPLIT 4

// ---------------- scratch ----------------------------------------------------
__device__ float g_Am[BATCH * CH * NMASK];            // [b][k][i]
__device__ float g_Bn[BATCH * CH * NCTX];             // [b][k][j]
__device__ float g_best[BATCH * NMASK * CH];
__device__ float g_mskn[BATCH * NMASK * CH];
__device__ float g_gen[BATCH * NMASK * CH];
__device__ float g_part[NSPLIT][BATCH * HW];
__device__ float g_invall[BATCH * HW];
__device__ float g_n2[BATCH * HW];                    // |col|^2 at every point
__device__ float g_invc[BATCH * NCTX];
__device__ float g_invm[BATCH * NMASK];
__device__ float g_maxc[BATCH * NMASK];
__device__ float g_bn2[BATCH * NMASK];                // |best_i|^2
__device__ unsigned long long g_packed[BATCH * NMASK];
__device__ int   g_imask[HW];

// ---------------- helpers ----------------------------------------------------
__device__ __forceinline__ void cp16(void* sdst, const void* gsrc) {
    unsigned saddr = (unsigned)__cvta_generic_to_shared(sdst);
    asm volatile("cp.async.ca.shared.global [%0], [%1], 16;\n" :: "r"(saddr), "l"(gsrc));
}
__device__ __forceinline__ unsigned ford(float f) {
    unsigned u = __float_as_uint(f);
    return (u & 0x80000000u) ? ~u : (u | 0x80000000u);
}
__device__ __forceinline__ float frcp(float x) {
    float r; asm("rcp.approx.f32 %0, %1;" : "=f"(r) : "f"(x)); return r;
}
__device__ __forceinline__ float frsq(float x) {
    float r; asm("rsqrt.approx.f32 %0, %1;" : "=f"(r) : "f"(x)); return r;
}
__device__ __forceinline__ void st_release_s32(volatile int* p, int v) {
    unsigned a = (unsigned)__cvta_generic_to_shared((void*)p);
    asm volatile("st.release.cta.shared.b32 [%0], %1;" :: "r"(a), "r"(v) : "memory");
}
__device__ __forceinline__ int ld_acquire_s32(volatile int* p) {
    unsigned a = (unsigned)__cvta_generic_to_shared((void*)p);
    int v;
    asm volatile("ld.acquire.cta.shared.b32 %0, [%1];" : "=r"(v) : "r"(a) : "memory");
    return v;
}

// ---------------- K1a/K1b: column norms -------------------------------------
__global__ void k_part(const float* __restrict__ x) {
    int p = blockIdx.x * 256 + threadIdx.x;
    int b = blockIdx.y;
    int z = blockIdx.z;
    const float* base = x + ((size_t)b * CH + (size_t)z * (CH / NSPLIT)) * HW + p;
    float s = 0.f;
#pragma unroll 8
    for (int c = 0; c < CH / NSPLIT; c++) {
        float v = base[(size_t)c * HW];
        s += v * v;
    }
    g_part[z][b * HW + p] = s;
}
__global__ void k_invall() {
    int i = blockIdx.x * 256 + threadIdx.x;
    float s = g_part[0][i] + g_part[1][i] + g_part[2][i] + g_part[3][i];
    g_n2[i] = s;
    g_invall[i] = 1.f / (sqrtf(s) + EPSF);
}

// ---------------- K2: setup --------------------------------------------------
__global__ void k_setup(const int* __restrict__ np, const int* __restrict__ mp) {
    int t = threadIdx.x;  // 1024, 1 block
    for (int p = t; p < HW; p += 1024) g_imask[p] = -1;
    __syncthreads();
    g_imask[mp[t]] = t;
    for (int i = t; i < BATCH * NMASK; i += 1024) g_packed[i] = 0ull;
    for (int i = t; i < BATCH * NMASK; i += 1024) {
        int b = i / NMASK;
        g_invm[i] = g_invall[b * HW + mp[i % NMASK]];
    }
    for (int j = t; j < BATCH * NCTX; j += 1024) {
        int b = j / NCTX;
        g_invc[j] = g_invall[b * HW + np[j % NCTX]];
    }
}

// ---------------- K3: gather A/B, K-major ------------------------------------
__global__ void k_gather(const float* __restrict__ x,
                         const int* __restrict__ np, const int* __restrict__ mp) {
    int k = blockIdx.x;
    int b = blockIdx.y;
    int t = threadIdx.x;        // 1024
    const float* row = x + ((size_t)b * CH + k) * HW;
    g_Am[((size_t)b * CH + k) * NMASK + t] = row[mp[t]];
#pragma unroll
    for (int j = t; j < NCTX; j += 1024)
        g_Bn[((size_t)b * CH + k) * NCTX + j] = row[np[j]];
}

// ---------------- K4: fp32 GEMM (2-stage cp.async, f32x2 FFMA) --------------
#define BM 128
#define BN 128
#define BK 16
#define NT (CH / BK)

__global__ void __launch_bounds__(256, 2) k_gemm() {
    __shared__ __align__(16) float As[2][BK][BM];
    __shared__ __align__(16) float Bs[2][BK][BN];

    int b  = blockIdx.z;
    int i0 = blockIdx.y * BM;
    int j0 = blockIdx.x * BN;
    int tid = threadIdx.x;
    int tx = tid & 15, ty = tid >> 4;
    int cA = tx * 4;

    const float* A  = g_Am + (size_t)b * CH * NMASK + i0;
    const float* Bp = g_Bn + (size_t)b * CH * NCTX  + j0;

    unsigned long long acc[8][4];
#pragma unroll
    for (int r = 0; r < 8; r++)
#pragma unroll
        for (int q = 0; q < 4; q++) acc[r][q] = 0ull;

#define COPY_TILE(t)                                                          \
    do {                                                                      \
        int s_ = (t) & 1;                                                     \
        const float* ga = A  + (size_t)((t) * BK + ty) * NMASK + cA;          \
        const float* gb = Bp + (size_t)((t) * BK + ty) * NCTX  + cA;          \
        cp16(&As[s_][ty][cA],      ga);                                       \
        cp16(&As[s_][ty][64 + cA], ga + 64);                                  \
        cp16(&Bs[s_][ty][cA],      gb);                                       \
        cp16(&Bs[s_][ty][64 + cA], gb + 64);                                  \
        asm volatile("cp.async.commit_group;\n");                             \
    } while (0)

    COPY_TILE(0);
    COPY_TILE(1);

#pragma unroll 1
    for (int t = 0; t < NT; t++) {
        if (t < NT - 1) asm volatile("cp.async.wait_group 1;\n");
        else            asm volatile("cp.async.wait_group 0;\n");
        __syncthreads();
        int s = t & 1;
#pragma unroll
        for (int kk = 0; kk < BK; kk++) {
            float4 a0 = *(const float4*)&As[s][kk][ty * 4];
            float4 a1 = *(const float4*)&As[s][kk][64 + ty * 4];
            ulonglong2 bv0 = *(const ulonglong2*)&Bs[s][kk][tx * 4];
            ulonglong2 bv1 = *(const ulonglong2*)&Bs[s][kk][64 + tx * 4];
            float ar[8] = {a0.x, a0.y, a0.z, a0.w, a1.x, a1.y, a1.z, a1.w};
            unsigned long long bq[4] = {bv0.x, bv0.y, bv1.x, bv1.y};
#pragma unroll
            for (int r = 0; r < 8; r++) {
                unsigned long long a2;
                asm("mov.b64 %0, {%1, %1};" : "=l"(a2) : "r"(__float_as_uint(ar[r])));
#pragma unroll
                for (int q = 0; q < 4; q++)
                    asm("fma.rn.f32x2 %0, %1, %2, %0;"
                        : "+l"(acc[r][q]) : "l"(a2), "l"(bq[q]));
            }
        }
        __syncthreads();
        if (t + 2 < NT) COPY_TILE(t + 2);
    }

    float invc[8];
#pragma unroll
    for (int g = 0; g < 2; g++)
#pragma unroll
        for (int e = 0; e < 4; e++)
            invc[g * 4 + e] = g_invc[b * NCTX + j0 + g * 64 + tx * 4 + e];

#pragma unroll
    for (int r = 0; r < 8; r++) {
        int irow = (r < 4) ? (ty * 4 + r) : (64 + ty * 4 + (r - 4));
        unsigned long long bp = 0ull;
#pragma unroll
        for (int q = 0; q < 4; q++) {
            float lo = __uint_as_float((unsigned)acc[r][q]);
            float hi = __uint_as_float((unsigned)(acc[r][q] >> 32));
            float v0 = lo * invc[q * 2];
            float v1 = hi * invc[q * 2 + 1];
            int jg = j0 + ((q >> 1) * 64) + tx * 4 + (q & 1) * 2;
            unsigned long long p0 = ((unsigned long long)ford(v0) << 32) | (unsigned)(~(unsigned)jg);
            unsigned long long p1 = ((unsigned long long)ford(v1) << 32) | (unsigned)(~(unsigned)(jg + 1));
            if (p0 > bp) bp = p0;
            if (p1 > bp) bp = p1;
        }
#pragma unroll
        for (int o = 1; o < 16; o <<= 1) {
            unsigned long long other = __shfl_xor_sync(0xffffffffu, bp, o);
            if (other > bp) bp = other;
        }
        if (tx == 0) atomicMax(&g_packed[b * NMASK + i0 + irow], bp);
    }
}

// ---------------- K5: finalize pick + gather + |best|^2 ----------------------
__global__ void k_finalize(const int* __restrict__ np) {
    int i = blockIdx.x;
    int b = blockIdx.y;
    int t = threadIdx.x;  // 256
    __shared__ int s_j;
    __shared__ float s_invm;
    if (t == 0) {
        unsigned long long pk = g_packed[b * NMASK + i];
        unsigned j  = ~(unsigned)pk;
        unsigned ov = (unsigned)(pk >> 32);
        unsigned fb = (ov & 0x80000000u) ? (ov & 0x7fffffffu) : ~ov;
        float val = __uint_as_float(fb);
        float im  = g_invm[b * NMASK + i];
        g_maxc[b * NMASK + i] = val * im;
        g_bn2[b * NMASK + i] = g_n2[b * HW + np[j]];
        s_j = (int)j;
        s_invm = im;
    }
    __syncthreads();
    int jj = s_j;
    float im = s_invm;
    const float* Am = g_Am + (size_t)b * CH * NMASK;
    const float* Bn = g_Bn + (size_t)b * CH * NCTX;
    size_t o = ((size_t)b * NMASK + i) * CH;
#pragma unroll
    for (int c = t; c < CH; c += 256) {
        g_best[o + c] = Bn[(size_t)c * NCTX + jj];
        g_mskn[o + c] = Am[(size_t)c * NMASK + i] * im;
    }
}

// ---------------- K6: scan v4 -------------------------------------------------
// warp 0 consumer: short dependent chain (incremental-norm recurrence moves
//   rsqrt/rcp(nrm) off the critical path); warp 1 producer: all cp.async.
// Handshake amortized over 4-step groups via monotonic counters.
#define NRING 16
#define NG (NMASK / 4)

struct ScanState {
    float s1;    // |q|^2 (recurrence)
    float rnd;   // 1/(nrm+eps), precomputed in previous step's shadow
};

__device__ __forceinline__ void scan_step(
    int i, float mx, float bn2, float* q, ScanState& st,
    const float (*ring)[2][CH], float* GE, size_t lo)
{
    int s = i & (NRING - 1);
    float mn[16], bs[16];
#pragma unroll
    for (int u = 0; u < 4; u++) {
        float4 a = *(const float4*)&ring[s][0][lo + u * 4];
        mn[u*4+0]=a.x; mn[u*4+1]=a.y; mn[u*4+2]=a.z; mn[u*4+3]=a.w;
        float4 c = *(const float4*)&ring[s][1][lo + u * 4];
        bs[u*4+0]=c.x; bs[u*4+1]=c.y; bs[u*4+2]=c.z; bs[u*4+3]=c.w;
    }
    // two dots with q: s2 = <mn,q>, c = <bs,q>
    float p2[8], pc[8];
#pragma unroll
    for (int e = 0; e < 8; e++) {
        p2[e] = __fmaf_rn(mn[e], q[e], mn[e + 8] * q[e + 8]);
        pc[e] = __fmaf_rn(bs[e], q[e], bs[e + 8] * q[e + 8]);
    }
#pragma unroll
    for (int w = 4; w; w >>= 1)
#pragma unroll
        for (int e = 0; e < w; e++) { p2[e] += p2[e + w]; pc[e] += pc[e + w]; }
    float s2 = p2[0], c = pc[0];
#pragma unroll
    for (int o = 16; o; o >>= 1) {
        s2 += __shfl_xor_sync(0xffffffffu, s2, o);
        c  += __shfl_xor_sync(0xffffffffu, c,  o);
    }
    // critical tail: d = max(s2,0)/(nrm+eps) using precomputed rnd
    float s2p = fmaxf(s2, 0.f);
    float d   = s2p * st.rnd;
    float T   = d + mx + EPSF;
    float rT  = frcp(T);
    float w1 = d * rT, w2 = mx * rT;
#pragma unroll
    for (int e = 0; e < 16; e++) q[e] = __fmaf_rn(w1, q[e], w2 * bs[e]);
    float* ge = GE + (size_t)i * CH + lo;
#pragma unroll
    for (int u = 0; u < 4; u++) {
        float4 w;
        w.x = q[u*4+0]; w.y = q[u*4+1]; w.z = q[u*4+2]; w.w = q[u*4+3];
        *(float4*)(ge + u * 4) = w;
    }
    // shadow tail (hidden under next step's LDS/partials/butterfly):
    float aa = w1 * w1, ab = w1 * w2, bb = w2 * w2;
    st.s1 = __fmaf_rn(aa, st.s1, __fmaf_rn(2.f * ab, c, bb * bn2));
    float rs  = (st.s1 > 0.f) ? frsq(st.s1) : 0.f;
    float nrm = st.s1 * rs;
    st.rnd = frcp(nrm + EPSF);
}

__global__ void __launch_bounds__(64, 1) k_scan() {
    __shared__ __align__(16) float ring[NRING][2][CH];   // 64KB
    __shared__ int rflag;   // producer: monotonic "ready through step"
    __shared__ int cdone;   // consumer: monotonic "consumed through step"

    int b = blockIdx.x;
    int warp = threadIdx.x >> 5;
    int lane = threadIdx.x & 31;

    const float* MN  = g_mskn + (size_t)b * NMASK * CH;
    const float* BS  = g_best + (size_t)b * NMASK * CH;
    float*       GE  = g_gen  + (size_t)b * NMASK * CH;
    const float* MX  = g_maxc + b * NMASK;
    const float* BN2 = g_bn2  + b * NMASK;
    size_t lo = (size_t)lane * 16;

    if (threadIdx.x == 0) { rflag = -1; cdone = -1; }
    __syncthreads();

#define PRE(i, s)                                                             \
    do {                                                                      \
        const float* pm = MN + (size_t)(i) * CH + lo;                         \
        const float* pb = BS + (size_t)(i) * CH + lo;                         \
        cp16(&ring[s][0][lo],      pm);                                       \
        cp16(&ring[s][0][lo + 4],  pm + 4);                                   \
        cp16(&ring[s][0][lo + 8],  pm + 8);                                   \
        cp16(&ring[s][0][lo + 12], pm + 12);                                  \
        cp16(&ring[s][1][lo],      pb);                                       \
        cp16(&ring[s][1][lo + 4],  pb + 4);                                   \
        cp16(&ring[s][1][lo + 8],  pb + 8);                                   \
        cp16(&ring[s][1][lo + 12], pb + 12);                                  \
    } while (0)

    if (warp == 1) {
        // ---------------- producer: prologue = groups 0..3 (steps 0..15) ----
#pragma unroll
        for (int g = 0; g < 4; g++) {
#pragma unroll
            for (int k = 0; k < 4; k++) PRE(4 * g + k, (4 * g + k) & (NRING - 1));
            asm volatile("cp.async.commit_group;\n");
        }
#pragma unroll 1
        for (int g = 0; g < NG; g++) {
            // publish group g (its cp.async group retired)
            int rem = NG - 1 - g;
            if (rem >= 3)      asm volatile("cp.async.wait_group 3;\n");
            else if (rem == 2) asm volatile("cp.async.wait_group 2;\n");
            else if (rem == 1) asm volatile("cp.async.wait_group 1;\n");
            else               asm volatile("cp.async.wait_group 0;\n");
            __syncwarp();
            if (lane == 0) st_release_s32(&rflag, 4 * g + 3);
            // refill: group g+4 reuses group g's slots -> need consumer past g
            if (g + 4 < NG) {
                while (ld_acquire_s32(&cdone) < 4 * g + 3) { }
                int s0 = 4 * (g + 4);
#pragma unroll
                for (int k = 0; k < 4; k++) PRE(s0 + k, (s0 + k) & (NRING - 1));
                asm volatile("cp.async.commit_group;\n");
            }
        }
    } else {
        // ---------------- consumer ----------------
        float q[16];
#pragma unroll
        for (int e = 0; e < 16; e++) q[e] = 0.f;
        ScanState st;
        st.s1 = 0.f;
        st.rnd = frcp(EPSF);
        int ready = -1;
        float4 mx4 = *(const float4*)MX;
        float4 b24 = *(const float4*)BN2;

#pragma unroll 1
        for (int g = 0; g < NG; g++) {
            int i0 = g * 4;
            if (ready < i0 + 3) {
                do { ready = ld_acquire_s32(&rflag); } while (ready < i0 + 3);
            }
            float4 mx4n = mx4, b24n = b24;
            if (g + 1 < NG) {
                mx4n = *(const float4*)(MX + i0 + 4);
                b24n = *(const float4*)(BN2 + i0 + 4);
            }
            scan_step(i0 + 0, mx4.x, b24.x, q, st, ring, GE, lo);
            scan_step(i0 + 1, mx4.y, b24.y, q, st, ring, GE, lo);
            scan_step(i0 + 2, mx4.z, b24.z, q, st, ring, GE, lo);
            scan_step(i0 + 3, mx4.w, b24.w, q, st, ring, GE, lo);
            mx4 = mx4n; b24 = b24n;
            __syncwarp();
            if (lane == 0) st_release_s32(&cdone, i0 + 3);
        }
    }
}

// ---------------- K7: assemble output ---------------------------------------
__global__ void k_out(const float* __restrict__ x, float* __restrict__ out) {
    int idx = blockIdx.x * 256 + threadIdx.x;
    int p = idx & (HW - 1);
    int c = (idx >> 12) & (CH - 1);
    int b = idx >> 21;
    int mi = g_imask[p];
    float v = (mi >= 0) ? g_gen[(((size_t)b * NMASK) + mi) * CH + c] : x[idx];
    out[idx] = v;
}

// ---------------- launch -----------------------------------------------------
extern "C" void kernel_launch(void* const* d_in, const int* in_sizes, int n_in,
                              void* d_out, int out_size) {
    const float* x  = (const float*)d_in[0];
    const int*   np = (const int*)d_in[2];
    const int*   mp = (const int*)d_in[3];
    float*       out = (float*)d_out;

    k_part    <<<dim3(HW / 256, BATCH, NSPLIT), 256>>>(x);
    k_invall  <<<BATCH * HW / 256, 256>>>();
    k_setup   <<<1, 1024>>>(np, mp);
    k_gather  <<<dim3(CH, BATCH), 1024>>>(x, np, mp);
    k_gemm    <<<dim3(NCTX / BN, NMASK / BM, BATCH), 256>>>();
    k_finalize<<<dim3(NMASK, BATCH), 256>>>(np);
    k_scan    <<<BATCH, 64>>>();
    k_out     <<<(BATCH * CH * HW) / 256, 256>>>(x, out);
}